// round 1
// baseline (speedup 1.0000x reference)
#include <cuda_runtime.h>
#include <cuda_bf16.h>
#include <cstdint>

// ---------------------------------------------------------------------------
// Problem constants
// ---------------------------------------------------------------------------
#define LQ      22223
#define CDIM    256
#define NHEADS  8
#define HDIM    32
#define NLVL    4
#define NPTS    4

// Level spatial shapes and starts
__device__ __constant__ int c_H[NLVL]     = {100, 50, 25, 13};
__device__ __constant__ int c_W[NLVL]     = {167, 84, 42, 21};
__device__ __constant__ int c_start[NLVL] = {0, 16700, 20900, 21950};

// ---------------------------------------------------------------------------
// Scratch (device globals; no allocation allowed)
// ---------------------------------------------------------------------------
__device__ float g_v   [LQ * CDIM];   // value @ W_val + b_val
__device__ float g_off [LQ * CDIM];   // query @ W_off + b_off  (h,l,p,xy packed)
__device__ float g_attn[LQ * 128];    // softmaxed attention weights (h,l,p)
__device__ float g_mid [LQ * CDIM];   // sampled+weighted output, pre-W_out

// ---------------------------------------------------------------------------
// SGEMM: C = A(MxK) @ B(KxN) + bias(N), row-major, fp32.
// BM=64, BN=64, BK=16, 256 threads, 4x4 per thread.
// K multiple of 16, N multiple of 64; M has edge guards.
// ---------------------------------------------------------------------------
#define BM 64
#define BN 64
#define BK 16
#define TM 4
#define TN 4

__global__ __launch_bounds__(256) void sgemm_bias(
    const float* __restrict__ A, const float* __restrict__ B,
    const float* __restrict__ bias, float* __restrict__ C,
    int M, int N, int K)
{
    __shared__ float As[BK][BM];
    __shared__ float Bs[BK][BN];

    const int block_row = blockIdx.y * BM;
    const int block_col = blockIdx.x * BN;
    const int tid = threadIdx.x;
    const int tx = tid & 15;          // 0..15
    const int ty = tid >> 4;          // 0..15

    // A-tile load mapping: one float4 per thread
    const int a_row = tid >> 2;            // 0..63
    const int a_k   = (tid & 3) * 4;       // 0,4,8,12
    // B-tile load mapping: one float4 per thread
    const int b_row = tid >> 4;            // 0..15
    const int b_col = (tid & 15) * 4;      // 0..60

    float acc[TM][TN];
    #pragma unroll
    for (int i = 0; i < TM; i++)
        #pragma unroll
        for (int j = 0; j < TN; j++) acc[i][j] = 0.0f;

    const int gr = block_row + a_row;
    for (int k0 = 0; k0 < K; k0 += BK) {
        float4 av = make_float4(0.f, 0.f, 0.f, 0.f);
        if (gr < M)
            av = *reinterpret_cast<const float4*>(&A[(size_t)gr * K + k0 + a_k]);
        As[a_k + 0][a_row] = av.x;
        As[a_k + 1][a_row] = av.y;
        As[a_k + 2][a_row] = av.z;
        As[a_k + 3][a_row] = av.w;

        float4 bv = *reinterpret_cast<const float4*>(
            &B[(size_t)(k0 + b_row) * N + block_col + b_col]);
        *reinterpret_cast<float4*>(&Bs[b_row][b_col]) = bv;

        __syncthreads();

        #pragma unroll
        for (int k = 0; k < BK; k++) {
            float a[TM], b[TN];
            #pragma unroll
            for (int i = 0; i < TM; i++) a[i] = As[k][ty * TM + i];
            #pragma unroll
            for (int j = 0; j < TN; j++) b[j] = Bs[k][tx * TN + j];
            #pragma unroll
            for (int i = 0; i < TM; i++)
                #pragma unroll
                for (int j = 0; j < TN; j++)
                    acc[i][j] = fmaf(a[i], b[j], acc[i][j]);
        }
        __syncthreads();
    }

    #pragma unroll
    for (int i = 0; i < TM; i++) {
        const int row = block_row + ty * TM + i;
        if (row >= M) continue;
        #pragma unroll
        for (int j = 0; j < TN; j++) {
            const int col = block_col + tx * TN + j;
            C[(size_t)row * N + col] = acc[i][j] + bias[col];
        }
    }
}

// ---------------------------------------------------------------------------
// Softmax over 16 contiguous logits per (q, head). In-place on g_attn.
// rows = LQ * NHEADS
// ---------------------------------------------------------------------------
__global__ void softmax16(float* __restrict__ a, int rows)
{
    const int r = blockIdx.x * blockDim.x + threadIdx.x;
    if (r >= rows) return;
    float* p = a + (size_t)r * 16;
    float v[16];
    float m = -1e30f;
    #pragma unroll
    for (int i = 0; i < 16; i++) { v[i] = p[i]; m = fmaxf(m, v[i]); }
    float s = 0.f;
    #pragma unroll
    for (int i = 0; i < 16; i++) { v[i] = __expf(v[i] - m); s += v[i]; }
    const float inv = 1.0f / s;
    #pragma unroll
    for (int i = 0; i < 16; i++) p[i] = v[i] * inv;
}

// ---------------------------------------------------------------------------
// Deformable sampling: one warp per (q, head), lane = channel d.
// Corner gathers are 32 contiguous floats (128B) -> fully coalesced; v fits
// in L2 so this is L2-bandwidth bound.
// ---------------------------------------------------------------------------
__global__ __launch_bounds__(256) void sample_kernel(
    const float* __restrict__ v, const float* __restrict__ off,
    const float* __restrict__ attn, const float* __restrict__ ref,
    float* __restrict__ mid)
{
    const int q    = blockIdx.x;
    const int h    = threadIdx.x >> 5;
    const int lane = threadIdx.x & 31;

    const float* offq = off  + (size_t)q * CDIM + h * 32;
    const float* attq = attn + (size_t)q * 128 + h * 16;
    const float* refq = ref  + (size_t)q * 16;

    float acc = 0.0f;

    #pragma unroll
    for (int l = 0; l < NLVL; l++) {
        const float cx = refq[l * 4 + 0];
        const float cy = refq[l * 4 + 1];
        const float rw = refq[l * 4 + 2];
        const float rh = refq[l * 4 + 3];
        const int H = c_H[l], W = c_W[l];
        const int start = c_start[l];
        const float* vbase = v + ((size_t)start * CDIM) + h * 32 + lane;

        #pragma unroll
        for (int p = 0; p < NPTS; p++) {
            const float ox = offq[l * 8 + p * 2 + 0];
            const float oy = offq[l * 8 + p * 2 + 1];
            // loc = ref + off/NPTS * wh * 0.5 ; grid = 2*loc-1 ;
            // x = (gx+1)*0.5*W - 0.5 = loc_x*W - 0.5
            const float x = (cx + ox * 0.125f * rw) * (float)W - 0.5f;
            const float y = (cy + oy * 0.125f * rh) * (float)H - 0.5f;

            const float x0f = floorf(x), y0f = floorf(y);
            const int x0 = (int)x0f, y0 = (int)y0f;
            const float wx1 = x - x0f, wy1 = y - y0f;
            const float wx0 = 1.0f - wx1, wy0 = 1.0f - wy1;

            const bool vx0 = (x0 >= 0) && (x0 < W);
            const bool vx1 = (x0 + 1 >= 0) && (x0 + 1 < W);
            const bool vy0 = (y0 >= 0) && (y0 < H);
            const bool vy1 = (y0 + 1 >= 0) && (y0 + 1 < H);

            float s = 0.0f;
            if (vy0) {
                const float* rowp = vbase + (size_t)y0 * W * CDIM;
                if (vx0) s = fmaf(wy0 * wx0, rowp[(size_t)x0 * CDIM], s);
                if (vx1) s = fmaf(wy0 * wx1, rowp[(size_t)(x0 + 1) * CDIM], s);
            }
            if (vy1) {
                const float* rowp = vbase + (size_t)(y0 + 1) * W * CDIM;
                if (vx0) s = fmaf(wy1 * wx0, rowp[(size_t)x0 * CDIM], s);
                if (vx1) s = fmaf(wy1 * wx1, rowp[(size_t)(x0 + 1) * CDIM], s);
            }
            acc = fmaf(attq[l * 4 + p], s, acc);
        }
    }

    mid[(size_t)q * CDIM + h * 32 + lane] = acc;
}

// ---------------------------------------------------------------------------
// Launch
// ---------------------------------------------------------------------------
extern "C" void kernel_launch(void* const* d_in, const int* in_sizes, int n_in,
                              void* d_out, int out_size)
{
    const float* query  = (const float*)d_in[0];
    const float* ref    = (const float*)d_in[1];
    const float* value  = (const float*)d_in[2];
    const float* W_off  = (const float*)d_in[3];
    const float* b_off  = (const float*)d_in[4];
    const float* W_attn = (const float*)d_in[5];
    const float* b_attn = (const float*)d_in[6];
    const float* W_val  = (const float*)d_in[7];
    const float* b_val  = (const float*)d_in[8];
    const float* W_out  = (const float*)d_in[9];
    const float* b_out  = (const float*)d_in[10];
    float* out = (float*)d_out;

    float *gv, *goff, *gattn, *gmid;
    cudaGetSymbolAddress((void**)&gv,   g_v);
    cudaGetSymbolAddress((void**)&goff, g_off);
    cudaGetSymbolAddress((void**)&gattn,g_attn);
    cudaGetSymbolAddress((void**)&gmid, g_mid);

    const int M = LQ;
    dim3 g256((CDIM + BN - 1) / BN, (M + BM - 1) / BM);   // N=256
    dim3 g128((128  + BN - 1) / BN, (M + BM - 1) / BM);   // N=128

    // 1. v = value @ W_val + b_val
    sgemm_bias<<<g256, 256>>>(value, W_val, b_val, gv, M, CDIM, CDIM);
    // 2. off = query @ W_off + b_off
    sgemm_bias<<<g256, 256>>>(query, W_off, b_off, goff, M, CDIM, CDIM);
    // 3. attn logits = query @ W_attn + b_attn
    sgemm_bias<<<g128, 256>>>(query, W_attn, b_attn, gattn, M, 128, CDIM);
    // 4. softmax over 16 per (q,h)
    {
        int rows = LQ * NHEADS;
        int nb = (rows + 255) / 256;
        softmax16<<<nb, 256>>>(gattn, rows);
    }
    // 5. sampling
    sample_kernel<<<LQ, 256>>>(gv, goff, gattn, ref, gmid);
    // 6. out = mid @ W_out + b_out
    sgemm_bias<<<g256, 256>>>(gmid, W_out, b_out, out, M, CDIM, CDIM);
}